// round 1
// baseline (speedup 1.0000x reference)
#include <cuda_runtime.h>
#include <cuda_bf16.h>
#include <math.h>

// Problem dims
#define B_  16
#define C_  16
#define P_  512
#define D_  256

#define BCPD (B_*C_*P_*D_)   // 33,554,432
#define BPD  (B_*P_*D_)      // 2,097,152
#define BCPP (B_*C_*P_*P_)   // 67,108,864

// Scratch (device globals — no runtime allocation allowed)
__device__ float g_ctx[BCPD];
__device__ float g_q[BCPD];
__device__ float g_k[BCPD];
__device__ float g_v[BCPD];
__device__ float g_scores[BCPP];

// ---------------------------------------------------------------------------
// Kernel A: context[b,c,p,d] = (sum_c' aw[c',p,d]*q[b,c',p,d]) - aw[c,p,d]*q[b,c,p,d]
// One thread per (b,p,d); loops over C=16.
// ---------------------------------------------------------------------------
__global__ __launch_bounds__(256) void ctx_kernel(const float* __restrict__ q,
                                                  const float* __restrict__ aw,
                                                  float* __restrict__ ctx)
{
    int idx = blockIdx.x * blockDim.x + threadIdx.x;
    if (idx >= BPD) return;
    int d = idx & (D_ - 1);
    int p = (idx / D_) & (P_ - 1);
    int b = idx / (D_ * P_);

    float prod[C_];
    float acc = 0.f;
#pragma unroll
    for (int c = 0; c < C_; c++) {
        float w  = aw[((long)(c * P_ + p)) * D_ + d];
        float qq = q[((long)((b * C_ + c) * P_ + p)) * D_ + d];
        prod[c] = w * qq;
        acc += prod[c];
    }
#pragma unroll
    for (int c = 0; c < C_; c++) {
        ctx[((long)((b * C_ + c) * P_ + p)) * D_ + d] = acc - prod[c];
    }
}

// ---------------------------------------------------------------------------
// Batched SGEMM: O[z] = epilogue( A[z] @ B[bz] )  (128x128 tile, 8x8/thread)
//   A: M x K row-major
//   B: NN -> K x N row-major ;  NT -> N x K row-major (computes A @ B^T)
//   bz = (bMod>0) ? z % bMod : z
//   epilogue: v = acc (+ bias[n]); if RELU v=max(v,0); v *= scale
// Requires M%128==0, N%128==0, K%8==0.
// ---------------------------------------------------------------------------
template<bool TRANS_B, bool RELU, bool HAS_BIAS>
__global__ __launch_bounds__(256) void sgemm_kernel(
    const float* __restrict__ Aall, const float* __restrict__ Ball,
    const float* __restrict__ biasAll, float* __restrict__ Oall,
    int M, int N, int K,
    long strideA, long strideB, long strideO,
    int bMod, float scale)
{
    __shared__ float As[8][128];
    __shared__ float Bs[8][128];

    int z  = blockIdx.z;
    int bz = (bMod > 0) ? (z % bMod) : z;
    const float* A  = Aall + (long)z * strideA;
    const float* Bm = Ball + (long)bz * strideB;
    const float* bias = HAS_BIAS ? (biasAll + (long)bz * N) : nullptr;
    float* O = Oall + (long)z * strideO;

    const int m0 = blockIdx.y * 128;
    const int n0 = blockIdx.x * 128;

    const int t  = threadIdx.x;
    const int tx = t & 15;     // 0..15 -> column groups
    const int ty = t >> 4;     // 0..15 -> row groups

    float acc[8][8];
#pragma unroll
    for (int i = 0; i < 8; i++)
#pragma unroll
        for (int j = 0; j < 8; j++) acc[i][j] = 0.f;

    // A-tile load mapping: thread t -> row=t>>1, k4=(t&1)*4 (one float4 each)
    const int aRow = t >> 1;
    const int aK4  = (t & 1) * 4;
    // B NN mapping: k=t>>5, n4=(t&31)*4
    const int bK  = t >> 5;
    const int bN4 = (t & 31) * 4;
    // B NT mapping: n=t>>1, k4=(t&1)*4
    const int btN  = t >> 1;
    const int btK4 = (t & 1) * 4;

    for (int k0 = 0; k0 < K; k0 += 8) {
        float4 av = *reinterpret_cast<const float4*>(
            &A[(long)(m0 + aRow) * K + k0 + aK4]);
        As[aK4 + 0][aRow] = av.x;
        As[aK4 + 1][aRow] = av.y;
        As[aK4 + 2][aRow] = av.z;
        As[aK4 + 3][aRow] = av.w;

        if (TRANS_B) {
            float4 bv = *reinterpret_cast<const float4*>(
                &Bm[(long)(n0 + btN) * K + k0 + btK4]);
            Bs[btK4 + 0][btN] = bv.x;
            Bs[btK4 + 1][btN] = bv.y;
            Bs[btK4 + 2][btN] = bv.z;
            Bs[btK4 + 3][btN] = bv.w;
        } else {
            float4 bv = *reinterpret_cast<const float4*>(
                &Bm[(long)(k0 + bK) * N + n0 + bN4]);
            *reinterpret_cast<float4*>(&Bs[bK][bN4]) = bv;
        }
        __syncthreads();

#pragma unroll
        for (int kk = 0; kk < 8; kk++) {
            float a[8], b[8];
            float4 a0 = *reinterpret_cast<const float4*>(&As[kk][ty * 4]);
            float4 a1 = *reinterpret_cast<const float4*>(&As[kk][64 + ty * 4]);
            float4 b0 = *reinterpret_cast<const float4*>(&Bs[kk][tx * 4]);
            float4 b1 = *reinterpret_cast<const float4*>(&Bs[kk][64 + tx * 4]);
            a[0]=a0.x; a[1]=a0.y; a[2]=a0.z; a[3]=a0.w;
            a[4]=a1.x; a[5]=a1.y; a[6]=a1.z; a[7]=a1.w;
            b[0]=b0.x; b[1]=b0.y; b[2]=b0.z; b[3]=b0.w;
            b[4]=b1.x; b[5]=b1.y; b[6]=b1.z; b[7]=b1.w;
#pragma unroll
            for (int i = 0; i < 8; i++)
#pragma unroll
                for (int j = 0; j < 8; j++)
                    acc[i][j] = fmaf(a[i], b[j], acc[i][j]);
        }
        __syncthreads();
    }

    // Epilogue
#pragma unroll
    for (int i = 0; i < 8; i++) {
        int m = m0 + ((i < 4) ? (ty * 4 + i) : (64 + ty * 4 + (i - 4)));
#pragma unroll
        for (int jh = 0; jh < 2; jh++) {
            int nbase = n0 + jh * 64 + tx * 4;
            float4 ov;
            float vv[4];
#pragma unroll
            for (int j = 0; j < 4; j++) {
                float v = acc[i][jh * 4 + j];
                if (HAS_BIAS) v += bias[nbase + j];
                if (RELU)     v = fmaxf(v, 0.f);
                vv[j] = v * scale;
            }
            ov.x = vv[0]; ov.y = vv[1]; ov.z = vv[2]; ov.w = vv[3];
            *reinterpret_cast<float4*>(&O[(long)m * N + nbase]) = ov;
        }
    }
}

// ---------------------------------------------------------------------------
// Row softmax over 512 columns: one warp per row, 16 elems per lane.
// ---------------------------------------------------------------------------
__global__ __launch_bounds__(256) void softmax_kernel(float* __restrict__ s, long nrows)
{
    long row = (long)blockIdx.x * (blockDim.x / 32) + (threadIdx.x >> 5);
    if (row >= nrows) return;
    int lane = threadIdx.x & 31;
    float* r = s + row * (long)P_;

    float vals[16];
    float mx = -INFINITY;
#pragma unroll
    for (int i = 0; i < 16; i++) {
        vals[i] = r[lane + i * 32];
        mx = fmaxf(mx, vals[i]);
    }
#pragma unroll
    for (int o = 16; o > 0; o >>= 1)
        mx = fmaxf(mx, __shfl_xor_sync(0xffffffffu, mx, o));

    float sum = 0.f;
#pragma unroll
    for (int i = 0; i < 16; i++) {
        vals[i] = __expf(vals[i] - mx);
        sum += vals[i];
    }
#pragma unroll
    for (int o = 16; o > 0; o >>= 1)
        sum += __shfl_xor_sync(0xffffffffu, sum, o);

    float inv = 1.f / sum;
#pragma unroll
    for (int i = 0; i < 16; i++)
        r[lane + i * 32] = vals[i] * inv;
}

// ---------------------------------------------------------------------------
// Launcher
// Inputs (metadata order):
//  0 query (B,C,P,D) 1 attn_weight (C,P,D) 2 q_proj_weight (C,D,D)
//  3 k_proj_weight   4 v_proj_weight       5 q_proj_bias (C,1,D)
//  6 k_proj_bias     7 v_proj_bias
// Output: (B,C,P,D) float32
// ---------------------------------------------------------------------------
extern "C" void kernel_launch(void* const* d_in, const int* in_sizes, int n_in,
                              void* d_out, int out_size)
{
    const float* query = (const float*)d_in[0];
    const float* aw    = (const float*)d_in[1];
    const float* qw    = (const float*)d_in[2];
    const float* kw    = (const float*)d_in[3];
    const float* vw    = (const float*)d_in[4];
    const float* qb    = (const float*)d_in[5];
    const float* kb    = (const float*)d_in[6];
    const float* vb    = (const float*)d_in[7];
    float* out = (float*)d_out;

    float* ctx;    cudaGetSymbolAddress((void**)&ctx,    g_ctx);
    float* qbuf;   cudaGetSymbolAddress((void**)&qbuf,   g_q);
    float* kbuf;   cudaGetSymbolAddress((void**)&kbuf,   g_k);
    float* vbuf;   cudaGetSymbolAddress((void**)&vbuf,   g_v);
    float* scores; cudaGetSymbolAddress((void**)&scores, g_scores);

    // 1) context
    ctx_kernel<<<BPD / 256, 256>>>(query, aw, ctx);

    const float qscale = 0.0625f;   // D^-0.5 = 1/16
    const long  sPD = (long)P_ * D_;
    const long  sDD = (long)D_ * D_;
    const long  sPP = (long)P_ * P_;
    const int   Z   = B_ * C_;

    // 2) q = relu(query @ Wq + bq) * qscale     M=512 N=256 K=256
    {
        dim3 grid(D_ / 128, P_ / 128, Z);
        sgemm_kernel<false, true, true><<<grid, 256>>>(
            query, qw, qb, qbuf, P_, D_, D_, sPD, sDD, sPD, C_, qscale);
    }
    // 3) k = relu(ctx @ Wk + bk)
    {
        dim3 grid(D_ / 128, P_ / 128, Z);
        sgemm_kernel<false, true, true><<<grid, 256>>>(
            ctx, kw, kb, kbuf, P_, D_, D_, sPD, sDD, sPD, C_, 1.0f);
    }
    // 4) v = relu(ctx @ Wv + bv)
    {
        dim3 grid(D_ / 128, P_ / 128, Z);
        sgemm_kernel<false, true, true><<<grid, 256>>>(
            ctx, vw, vb, vbuf, P_, D_, D_, sPD, sDD, sPD, C_, 1.0f);
    }
    // 5) scores = q @ k^T     M=512 N=512 K=256  (NT)
    {
        dim3 grid(P_ / 128, P_ / 128, Z);
        sgemm_kernel<true, false, false><<<grid, 256>>>(
            qbuf, kbuf, nullptr, scores, P_, P_, D_, sPD, sPD, sPP, 0, 1.0f);
    }
    // 6) softmax rows (B*C*P rows of 512)
    {
        long nrows = (long)B_ * C_ * P_;
        int blocks = (int)((nrows + 7) / 8);
        softmax_kernel<<<blocks, 256>>>(scores, nrows);
    }
    // 7) out = attn @ v       M=512 N=256 K=512  (NN)
    {
        dim3 grid(D_ / 128, P_ / 128, Z);
        sgemm_kernel<false, false, false><<<grid, 256>>>(
            scores, vbuf, nullptr, out, P_, D_, P_, sPP, sPD, sPD, 0, 1.0f);
    }
}

// round 4
// speedup vs baseline: 2.1917x; 2.1917x over previous
#include <cuda_runtime.h>
#include <cuda_bf16.h>
#include <cstdint>
#include <math.h>

// ---------------------------------------------------------------- dims
#define B_  16
#define C_  16
#define P_  512
#define D_  256
#define Z_  (B_*C_)            // 256 batches
#define BCPD (B_*C_*P_*D_)     // 33,554,432
#define BPD  (B_*P_*D_)        // 2,097,152
#define BCPP (B_*C_*P_*P_)     // 67,108,864
#define WELEM (C_*D_*D_)       // 1,048,576

// ---------------------------------------------------------------- scratch
__device__ __nv_bfloat16 g_qry_hi[BCPD], g_qry_lo[BCPD];
__device__ __nv_bfloat16 g_ctx_hi[BCPD], g_ctx_lo[BCPD];
__device__ __nv_bfloat16 g_q_hi[BCPD],   g_q_lo[BCPD];
__device__ __nv_bfloat16 g_k_hi[BCPD],   g_k_lo[BCPD];
__device__ __nv_bfloat16 g_vT_hi[BCPD],  g_vT_lo[BCPD];
__device__ __nv_bfloat16 g_attn_hi[BCPP], g_attn_lo[BCPP];
__device__ float g_scores[BCPP];
__device__ __nv_bfloat16 g_wqT_hi[WELEM], g_wqT_lo[WELEM];
__device__ __nv_bfloat16 g_wkT_hi[WELEM], g_wkT_lo[WELEM];
__device__ __nv_bfloat16 g_wvT_hi[WELEM], g_wvT_lo[WELEM];

// ---------------------------------------------------------------- helpers
__device__ __forceinline__ uint32_t smem_u32(const void* p) {
    uint32_t a;
    asm("{ .reg .u64 t; cvta.to.shared.u64 t, %1; cvt.u32.u64 %0, t; }" : "=r"(a) : "l"(p));
    return a;
}

#define CP16(saddr, gaddr) \
    asm volatile("cp.async.cg.shared.global [%0], [%1], 16;" :: "r"(saddr), "l"(gaddr) : "memory")
#define CP_COMMIT() asm volatile("cp.async.commit_group;" ::: "memory")
#define CP_WAIT1()  asm volatile("cp.async.wait_group 1;" ::: "memory")
#define CP_WAIT0()  asm volatile("cp.async.wait_group 0;" ::: "memory")

#define LDSM4(r0, r1, r2, r3, addr) \
    asm volatile("ldmatrix.sync.aligned.m8n8.x4.shared.b16 {%0,%1,%2,%3}, [%4];" \
        : "=r"(r0), "=r"(r1), "=r"(r2), "=r"(r3) : "r"(addr))

#define MMA16816(c, a, b) \
    asm volatile("mma.sync.aligned.m16n8k16.row.col.f32.bf16.bf16.f32 " \
        "{%0,%1,%2,%3}, {%4,%5,%6,%7}, {%8,%9}, {%0,%1,%2,%3};" \
        : "+f"((c)[0]), "+f"((c)[1]), "+f"((c)[2]), "+f"((c)[3]) \
        : "r"((a)[0]), "r"((a)[1]), "r"((a)[2]), "r"((a)[3]), "r"((b)[0]), "r"((b)[1]))

__device__ __forceinline__ void split2(float v, __nv_bfloat16& h, __nv_bfloat16& l) {
    h = __float2bfloat16(v);
    l = __float2bfloat16(v - __bfloat162float(h));
}

// ---------------------------------------------------------------- smem layout
// Double-buffered operand stages: each stage = Ahi | Alo | Bhi | Blo, 8KB each.
#define STAGE_SZ  32768
#define OFF_AH    0
#define OFF_AL    8192
#define OFF_BH    16384
#define OFF_BL    24576
// Epilogue stage: 128 x 130 fp32 = 66560 bytes (reuses operand smem)
#define SMEM_SZ   66560
#define STG_LD    130

// ---------------------------------------------------------------- GEMM
// D[128x128] = (Ahi+Alo)(Bhi+Blo)^T via 3 bf16 passes, fp32 accumulate.
// A: [z][M][K] bf16 K-major; B: [bz][N][K] bf16 K-major.
// Epilogue: (+bias[n], relu, *scale) then either split->bf16 hi/lo (opt.
// transposed as Out[z][N][M]) or plain fp32.
template<bool HAS_BIAS, bool OUT_SPLIT, bool TRANS_OUT>
__global__ __launch_bounds__(256, 2)
void mma_gemm(const __nv_bfloat16* __restrict__ Ahi, const __nv_bfloat16* __restrict__ Alo,
              const __nv_bfloat16* __restrict__ Bhi, const __nv_bfloat16* __restrict__ Blo,
              const float* __restrict__ bias,
              __nv_bfloat16* __restrict__ OutHi, __nv_bfloat16* __restrict__ OutLo,
              float* __restrict__ OutF,
              int M, int N, int K, int bMask, float scale)
{
    extern __shared__ char smem[];
    const uint32_t sb = smem_u32(smem);

    const int t    = threadIdx.x;
    const int wid  = t >> 5;
    const int lane = t & 31;
    const int wr   = wid >> 2;      // 0..1  (64 rows each)
    const int wc   = wid & 3;       // 0..3  (32 cols each)

    const int z  = blockIdx.z;
    const int bz = z & bMask;
    const int m0 = blockIdx.y * 128;
    const int n0 = blockIdx.x * 128;

    const long Kb = (long)K * 2;    // row stride in bytes
    const char* gA_hi = (const char*)(Ahi + ((long)z  * M + m0) * K);
    const char* gA_lo = (const char*)(Alo + ((long)z  * M + m0) * K);
    const char* gB_hi = (const char*)(Bhi + ((long)bz * N + n0) * K);
    const char* gB_lo = (const char*)(Blo + ((long)bz * N + n0) * K);

    // per-thread cp.async mapping: id in [0,512) -> row=id>>2, chunk=id&3
    const int id0 = t, id1 = t + 256;
    const int r0_ = id0 >> 2, c0_ = id0 & 3;
    const int r1_ = id1 >> 2, c1_ = id1 & 3;
    const uint32_t so0 = r0_ * 64 + (((c0_ ^ ((r0_ >> 1) & 3))) << 4);
    const uint32_t so1 = r1_ * 64 + (((c1_ ^ ((r1_ >> 1) & 3))) << 4);
    const long go0base = (long)r0_ * Kb + c0_ * 16;
    const long go1base = (long)r1_ * Kb + c1_ * 16;

    // ldmatrix per-thread invariants
    // A: row = wr*64 + mi*16 + (lane&15); k chunk add = lane>>4
    uint32_t a_ro[4]; int a_sw[4];
#pragma unroll
    for (int mi = 0; mi < 4; mi++) {
        int row = wr * 64 + mi * 16 + (lane & 15);
        a_ro[mi] = row * 64;
        a_sw[mi] = (row >> 1) & 3;
    }
    const int a_kc = lane >> 4;          // 0/1
    // B: row = wc*32 + nj*16 + (lane&7) + ((lane>=16)?8:0); k add = (lane>>3)&1
    uint32_t b_ro[2]; int b_sw[2];
#pragma unroll
    for (int nj = 0; nj < 2; nj++) {
        int row = wc * 32 + nj * 16 + (lane & 7) + ((lane >> 4) << 3);
        b_ro[nj] = row * 64;
        b_sw[nj] = (row >> 1) & 3;
    }
    const int b_kc = (lane >> 3) & 1;    // 0/1

    float acc[4][4][4];
#pragma unroll
    for (int mi = 0; mi < 4; mi++)
#pragma unroll
        for (int ni = 0; ni < 4; ni++)
#pragma unroll
            for (int r = 0; r < 4; r++) acc[mi][ni][r] = 0.f;

    const int nch = K >> 5;

    // ---- async load of one k-chunk into a stage
    auto load_chunk = [&](int ch, int buf) {
        const long gk = (long)ch * 64;               // 32 elems * 2B
        const uint32_t s = sb + buf * STAGE_SZ;
        CP16(s + OFF_AH + so0, gA_hi + go0base + gk);
        CP16(s + OFF_AH + so1, gA_hi + go1base + gk);
        CP16(s + OFF_AL + so0, gA_lo + go0base + gk);
        CP16(s + OFF_AL + so1, gA_lo + go1base + gk);
        CP16(s + OFF_BH + so0, gB_hi + go0base + gk);
        CP16(s + OFF_BH + so1, gB_hi + go1base + gk);
        CP16(s + OFF_BL + so0, gB_lo + go0base + gk);
        CP16(s + OFF_BL + so1, gB_lo + go1base + gk);
        CP_COMMIT();
    };

    load_chunk(0, 0);

    for (int ch = 0; ch < nch; ch++) {
        const int buf = ch & 1;
        if (ch + 1 < nch) { load_chunk(ch + 1, (ch + 1) & 1); CP_WAIT1(); }
        else              { CP_WAIT0(); }
        __syncthreads();

        const uint32_t sAH = sb + buf * STAGE_SZ + OFF_AH;
        const uint32_t sAL = sb + buf * STAGE_SZ + OFF_AL;
        const uint32_t sBH = sb + buf * STAGE_SZ + OFF_BH;
        const uint32_t sBL = sb + buf * STAGE_SZ + OFF_BL;

#pragma unroll
        for (int ks = 0; ks < 2; ks++) {
            const int kcA = ks * 2 + a_kc;
            const int kcB = ks * 2 + b_kc;

            uint32_t a[4][4], bh[4][2], bl[4][2];
#pragma unroll
            for (int mi = 0; mi < 4; mi++) {
                uint32_t ad = sAH + a_ro[mi] + (((uint32_t)(kcA ^ a_sw[mi])) << 4);
                LDSM4(a[mi][0], a[mi][1], a[mi][2], a[mi][3], ad);
            }
#pragma unroll
            for (int nj = 0; nj < 2; nj++) {
                uint32_t off = b_ro[nj] + (((uint32_t)(kcB ^ b_sw[nj])) << 4);
                LDSM4(bh[nj*2][0], bh[nj*2][1], bh[nj*2+1][0], bh[nj*2+1][1], sBH + off);
                LDSM4(bl[nj*2][0], bl[nj*2][1], bl[nj*2+1][0], bl[nj*2+1][1], sBL + off);
            }
            // pass 1: Ahi * Bhi
#pragma unroll
            for (int mi = 0; mi < 4; mi++)
#pragma unroll
                for (int ni = 0; ni < 4; ni++)
                    MMA16816(acc[mi][ni], a[mi], bh[ni]);
            // pass 2: Ahi * Blo
#pragma unroll
            for (int mi = 0; mi < 4; mi++)
#pragma unroll
                for (int ni = 0; ni < 4; ni++)
                    MMA16816(acc[mi][ni], a[mi], bl[ni]);
            // pass 3: Alo * Bhi  (reload a <- Alo)
#pragma unroll
            for (int mi = 0; mi < 4; mi++) {
                uint32_t ad = sAL + a_ro[mi] + (((uint32_t)(kcA ^ a_sw[mi])) << 4);
                LDSM4(a[mi][0], a[mi][1], a[mi][2], a[mi][3], ad);
            }
#pragma unroll
            for (int mi = 0; mi < 4; mi++)
#pragma unroll
                for (int ni = 0; ni < 4; ni++)
                    MMA16816(acc[mi][ni], a[mi], bh[ni]);
        }
        __syncthreads();
    }

    // ---------------- epilogue: acc -> padded smem stage
    float* stg = reinterpret_cast<float*>(smem);
    {
        const int grp = lane >> 2;
        const int tq  = lane & 3;
#pragma unroll
        for (int mi = 0; mi < 4; mi++) {
            const int m = wr * 64 + mi * 16 + grp;
#pragma unroll
            for (int ni = 0; ni < 4; ni++) {
                const int n = wc * 32 + ni * 8 + 2 * tq;
                stg[m * STG_LD + n]           = acc[mi][ni][0];
                stg[m * STG_LD + n + 1]       = acc[mi][ni][1];
                stg[(m + 8) * STG_LD + n]     = acc[mi][ni][2];
                stg[(m + 8) * STG_LD + n + 1] = acc[mi][ni][3];
            }
        }
    }
    __syncthreads();

    const float* brow = HAS_BIAS ? (bias + (long)bz * N + n0) : nullptr;

    if (OUT_SPLIT) {
        if (!TRANS_OUT) {
#pragma unroll
            for (int r = 0; r < 32; r++) {
                int idx = r * 256 + t;
                int m = idx >> 6, j = idx & 63;
                int n = 2 * j;
                float v0 = stg[m * STG_LD + n];
                float v1 = stg[m * STG_LD + n + 1];
                if (HAS_BIAS) {
                    v0 = fmaxf(v0 + brow[n], 0.f) * scale;
                    v1 = fmaxf(v1 + brow[n + 1], 0.f) * scale;
                }
                __nv_bfloat16 h0, l0, h1, l1;
                split2(v0, h0, l0); split2(v1, h1, l1);
                long base = ((long)z * M + m0 + m) * N + n0 + n;
                __nv_bfloat162 H; H.x = h0; H.y = h1;
                __nv_bfloat162 L; L.x = l0; L.y = l1;
                *reinterpret_cast<__nv_bfloat162*>(&OutHi[base]) = H;
                *reinterpret_cast<__nv_bfloat162*>(&OutLo[base]) = L;
            }
        } else {
            // Out[z][N][M]: row e (=n), col q (=m)
#pragma unroll
            for (int r = 0; r < 32; r++) {
                int idx = r * 256 + t;
                int e = idx >> 6, j = idx & 63;
                int q = 2 * j;
                float v0 = stg[q * STG_LD + e];
                float v1 = stg[(q + 1) * STG_LD + e];
                if (HAS_BIAS) {
                    float bv = brow[e];
                    v0 = fmaxf(v0 + bv, 0.f) * scale;
                    v1 = fmaxf(v1 + bv, 0.f) * scale;
                }
                __nv_bfloat16 h0, l0, h1, l1;
                split2(v0, h0, l0); split2(v1, h1, l1);
                long base = ((long)z * N + n0 + e) * M + m0 + q;
                __nv_bfloat162 H; H.x = h0; H.y = h1;
                __nv_bfloat162 L; L.x = l0; L.y = l1;
                *reinterpret_cast<__nv_bfloat162*>(&OutHi[base]) = H;
                *reinterpret_cast<__nv_bfloat162*>(&OutLo[base]) = L;
            }
        }
    } else {
#pragma unroll
        for (int r = 0; r < 64; r++) {
            int idx = r * 256 + t;
            int m = idx >> 7, n = idx & 127;
            float v = stg[m * STG_LD + n];
            if (HAS_BIAS) v = fmaxf(v + brow[n], 0.f) * scale;
            OutF[((long)z * M + m0 + m) * N + n0 + n] = v;
        }
    }
}

// ---------------------------------------------------------------- elementwise
__global__ __launch_bounds__(256) void split_query_kernel(const float* __restrict__ q,
        __nv_bfloat16* __restrict__ hi, __nv_bfloat16* __restrict__ lo)
{
    long i = (long)blockIdx.x * 256 + threadIdx.x;
    if (i >= BCPD) return;
    __nv_bfloat16 h, l;
    split2(q[i], h, l);
    hi[i] = h; lo[i] = l;
}

__global__ __launch_bounds__(256) void ctx_split_kernel(const float* __restrict__ q,
        const float* __restrict__ aw,
        __nv_bfloat16* __restrict__ hi, __nv_bfloat16* __restrict__ lo)
{
    int idx = blockIdx.x * 256 + threadIdx.x;
    if (idx >= BPD) return;
    int d = idx & (D_ - 1);
    int p = (idx / D_) & (P_ - 1);
    int b = idx / (D_ * P_);

    float prod[C_];
    float acc = 0.f;
#pragma unroll
    for (int c = 0; c < C_; c++) {
        float w  = aw[((long)(c * P_ + p)) * D_ + d];
        float qq = q[((long)((b * C_ + c) * P_ + p)) * D_ + d];
        prod[c] = w * qq;
        acc += prod[c];
    }
#pragma unroll
    for (int c = 0; c < C_; c++) {
        long o = ((long)((b * C_ + c) * P_ + p)) * D_ + d;
        __nv_bfloat16 h, l;
        split2(acc - prod[c], h, l);
        hi[o] = h; lo[o] = l;
    }
}

// W[c][d][e] -> WT[c][e][d] split to bf16
__global__ __launch_bounds__(256) void split_wT_kernel(const float* __restrict__ w,
        __nv_bfloat16* __restrict__ hiT, __nv_bfloat16* __restrict__ loT)
{
    int idx = blockIdx.x * 256 + threadIdx.x;
    if (idx >= WELEM) return;
    int e = idx & 255, d = (idx >> 8) & 255, c = idx >> 16;
    __nv_bfloat16 h, l;
    split2(w[idx], h, l);
    int o = (c << 16) | (e << 8) | d;
    hiT[o] = h; loT[o] = l;
}

// softmax over rows of 512 fp32, write bf16 hi/lo
__global__ __launch_bounds__(256) void softmax_split_kernel(const float* __restrict__ s,
        __nv_bfloat16* __restrict__ ahi, __nv_bfloat16* __restrict__ alo, long nrows)
{
    long row = (long)blockIdx.x * 8 + (threadIdx.x >> 5);
    if (row >= nrows) return;
    int lane = threadIdx.x & 31;
    const float* r = s + row * (long)P_;

    float vals[16];
    float mx = -INFINITY;
#pragma unroll
    for (int i = 0; i < 16; i++) {
        vals[i] = r[lane + i * 32];
        mx = fmaxf(mx, vals[i]);
    }
#pragma unroll
    for (int o = 16; o > 0; o >>= 1)
        mx = fmaxf(mx, __shfl_xor_sync(0xffffffffu, mx, o));
    float sum = 0.f;
#pragma unroll
    for (int i = 0; i < 16; i++) { vals[i] = __expf(vals[i] - mx); sum += vals[i]; }
#pragma unroll
    for (int o = 16; o > 0; o >>= 1)
        sum += __shfl_xor_sync(0xffffffffu, sum, o);
    float inv = 1.f / sum;
#pragma unroll
    for (int i = 0; i < 16; i++) {
        __nv_bfloat16 h, l;
        split2(vals[i] * inv, h, l);
        long o = row * (long)P_ + lane + i * 32;
        ahi[o] = h; alo[o] = l;
    }
}

// ---------------------------------------------------------------- launcher
extern "C" void kernel_launch(void* const* d_in, const int* in_sizes, int n_in,
                              void* d_out, int out_size)
{
    const float* query = (const float*)d_in[0];
    const float* aw    = (const float*)d_in[1];
    const float* qw    = (const float*)d_in[2];
    const float* kw    = (const float*)d_in[3];
    const float* vw    = (const float*)d_in[4];
    const float* qb    = (const float*)d_in[5];
    const float* kb    = (const float*)d_in[6];
    const float* vb    = (const float*)d_in[7];
    float* out = (float*)d_out;

    __nv_bfloat16 *qryH, *qryL, *ctxH, *ctxL, *qH, *qL, *kH, *kL, *vTH, *vTL;
    __nv_bfloat16 *atH, *atL, *wqH, *wqL, *wkH, *wkL, *wvH, *wvL;
    float* scores;
    cudaGetSymbolAddress((void**)&qryH, g_qry_hi); cudaGetSymbolAddress((void**)&qryL, g_qry_lo);
    cudaGetSymbolAddress((void**)&ctxH, g_ctx_hi); cudaGetSymbolAddress((void**)&ctxL, g_ctx_lo);
    cudaGetSymbolAddress((void**)&qH, g_q_hi);     cudaGetSymbolAddress((void**)&qL, g_q_lo);
    cudaGetSymbolAddress((void**)&kH, g_k_hi);     cudaGetSymbolAddress((void**)&kL, g_k_lo);
    cudaGetSymbolAddress((void**)&vTH, g_vT_hi);   cudaGetSymbolAddress((void**)&vTL, g_vT_lo);
    cudaGetSymbolAddress((void**)&atH, g_attn_hi); cudaGetSymbolAddress((void**)&atL, g_attn_lo);
    cudaGetSymbolAddress((void**)&wqH, g_wqT_hi);  cudaGetSymbolAddress((void**)&wqL, g_wqT_lo);
    cudaGetSymbolAddress((void**)&wkH, g_wkT_hi);  cudaGetSymbolAddress((void**)&wkL, g_wkT_lo);
    cudaGetSymbolAddress((void**)&wvH, g_wvT_hi);  cudaGetSymbolAddress((void**)&wvL, g_wvT_lo);
    cudaGetSymbolAddress((void**)&scores, g_scores);

    cudaFuncSetAttribute(mma_gemm<true,  true,  false>, cudaFuncAttributeMaxDynamicSharedMemorySize, SMEM_SZ);
    cudaFuncSetAttribute(mma_gemm<true,  true,  true >, cudaFuncAttributeMaxDynamicSharedMemorySize, SMEM_SZ);
    cudaFuncSetAttribute(mma_gemm<false, false, false>, cudaFuncAttributeMaxDynamicSharedMemorySize, SMEM_SZ);

    // 1) splits + context
    split_query_kernel<<<(BCPD + 255) / 256, 256>>>(query, qryH, qryL);
    ctx_split_kernel<<<(BPD + 255) / 256, 256>>>(query, aw, ctxH, ctxL);
    split_wT_kernel<<<(WELEM + 255) / 256, 256>>>(qw, wqH, wqL);
    split_wT_kernel<<<(WELEM + 255) / 256, 256>>>(kw, wkH, wkL);
    split_wT_kernel<<<(WELEM + 255) / 256, 256>>>(vw, wvH, wvL);

    const float qscale = 0.0625f;  // D^-1/2

    // 2) q = relu(query@Wq + bq) * qscale   M=512 N=256 K=256
    {
        dim3 g(D_ / 128, P_ / 128, Z_);
        mma_gemm<true, true, false><<<g, 256, SMEM_SZ>>>(
            qryH, qryL, wqH, wqL, qb, qH, qL, nullptr, P_, D_, D_, 15, qscale);
    }
    // 3) k = relu(ctx@Wk + bk)
    {
        dim3 g(D_ / 128, P_ / 128, Z_);
        mma_gemm<true, true, false><<<g, 256, SMEM_SZ>>>(
            ctxH, ctxL, wkH, wkL, kb, kH, kL, nullptr, P_, D_, D_, 15, 1.0f);
    }
    // 4) v = relu(ctx@Wv + bv), stored transposed [z][e][q]
    {
        dim3 g(D_ / 128, P_ / 128, Z_);
        mma_gemm<true, true, true><<<g, 256, SMEM_SZ>>>(
            ctxH, ctxL, wvH, wvL, vb, vTH, vTL, nullptr, P_, D_, D_, 15, 1.0f);
    }
    // 5) scores = q @ k^T   M=512 N=512 K=256
    {
        dim3 g(P_ / 128, P_ / 128, Z_);
        mma_gemm<false, false, false><<<g, 256, SMEM_SZ>>>(
            qH, qL, kH, kL, nullptr, nullptr, nullptr, scores, P_, P_, D_, 255, 1.0f);
    }
    // 6) softmax + split
    {
        long nrows = (long)B_ * C_ * P_;
        softmax_split_kernel<<<(int)((nrows + 7) / 8), 256>>>(scores, atH, atL, nrows);
    }
    // 7) out = attn @ v    M=512 N=256 K=512  (B = vT, K-major)
    {
        dim3 g(D_ / 128, P_ / 128, Z_);
        mma_gemm<false, false, false><<<g, 256, SMEM_SZ>>>(
            atH, atL, vTH, vTL, nullptr, nullptr, nullptr, out, P_, D_, P_, 255, 1.0f);
    }
}

// round 5
// speedup vs baseline: 3.3595x; 1.5329x over previous
#include <cuda_runtime.h>
#include <cuda_fp16.h>
#include <cstdint>
#include <math.h>

// ---------------------------------------------------------------- dims
#define B_  16
#define C_  16
#define P_  512
#define D_  256
#define Z_  (B_*C_)            // 256 batches
#define BCPD (B_*C_*P_*D_)     // 33,554,432
#define BPD  (B_*P_*D_)        // 2,097,152
#define BCPP (B_*C_*P_*P_)     // 67,108,864
#define WELEM (C_*D_*D_)       // 1,048,576

// ---------------------------------------------------------------- scratch
__device__ half g_qry_hi[BCPD], g_qry_lo[BCPD];
__device__ half g_ctx_hi[BCPD], g_ctx_lo[BCPD];
__device__ half g_q_hi[BCPD],   g_q_lo[BCPD];
__device__ half g_k[BCPD];
__device__ half g_vT_hi[BCPD],  g_vT_lo[BCPD];
__device__ half g_attn[BCPP];
__device__ float g_scores[BCPP];
__device__ half g_wqT[WELEM], g_wkT[WELEM], g_wvT[WELEM];

// ---------------------------------------------------------------- helpers
__device__ __forceinline__ uint32_t smem_u32(const void* p) {
    uint32_t a;
    asm("{ .reg .u64 t; cvta.to.shared.u64 t, %1; cvt.u32.u64 %0, t; }" : "=r"(a) : "l"(p));
    return a;
}

#define CP16(saddr, gaddr) \
    asm volatile("cp.async.cg.shared.global [%0], [%1], 16;" :: "r"(saddr), "l"(gaddr) : "memory")
#define CP_COMMIT() asm volatile("cp.async.commit_group;" ::: "memory")
#define CP_WAIT1()  asm volatile("cp.async.wait_group 1;" ::: "memory")
#define CP_WAIT0()  asm volatile("cp.async.wait_group 0;" ::: "memory")

#define LDSM4(r0, r1, r2, r3, addr) \
    asm volatile("ldmatrix.sync.aligned.m8n8.x4.shared.b16 {%0,%1,%2,%3}, [%4];" \
        : "=r"(r0), "=r"(r1), "=r"(r2), "=r"(r3) : "r"(addr))

#define MMAH(c, a, b) \
    asm volatile("mma.sync.aligned.m16n8k16.row.col.f32.f16.f16.f32 " \
        "{%0,%1,%2,%3}, {%4,%5,%6,%7}, {%8,%9}, {%0,%1,%2,%3};" \
        : "+f"((c)[0]), "+f"((c)[1]), "+f"((c)[2]), "+f"((c)[3]) \
        : "r"((a)[0]), "r"((a)[1]), "r"((a)[2]), "r"((a)[3]), "r"((b)[0]), "r"((b)[1]))

__device__ __forceinline__ void split2h(float v, half& h, half& l) {
    h = __float2half(v);
    l = __float2half(v - __half2float(h));
}

// ---------------------------------------------------------------- smem layout
// K-chunk = 64: each piece = 128 rows x 128B (SW swizzled). 3 pieces/stage.
#define OFF_P0   0
#define OFF_P1   16384
#define OFF_P2   32768
#define STAGE_SZ 49152
#define SMEM_SZ  98304      // 2 stages; epilogue (66560B) reuses this
#define STG_LD   130

// ---------------------------------------------------------------- GEMM
// 2-pass fp16 split GEMM, fp32 accumulate, CTA tile 128x128, K-chunk 64.
// SPLIT_B=0: D = (Ahi+Alo) @ B^T          (A0=Ahi, A1=Alo, B0=B)
// SPLIT_B=1: D = A @ (Bhi+Blo)^T          (A0=A,   B0=Bhi, B1=Blo)
// A: [z][M][K] fp16 K-major; B: [bz][N][K] fp16 K-major.
// OUT_MODE: 0 = fp32, 1 = split fp16 hi/lo, 2 = split fp16 transposed
//           (Out[z][N][M]), 3 = single fp16.
template<int SPLIT_B, int HAS_BIAS, int OUT_MODE>
__global__ __launch_bounds__(256, 2)
void mma_gemm(const half* __restrict__ A0, const half* __restrict__ A1,
              const half* __restrict__ B0, const half* __restrict__ B1,
              const float* __restrict__ bias,
              half* __restrict__ OutH, half* __restrict__ OutL,
              float* __restrict__ OutF,
              int M, int N, int K, int bMask, float scale)
{
    extern __shared__ char smem[];
    const uint32_t sb = smem_u32(smem);

    const int t    = threadIdx.x;
    const int wid  = t >> 5;
    const int lane = t & 31;
    const int wr   = wid >> 2;      // 0..1
    const int wc   = wid & 3;       // 0..3

    const int z  = blockIdx.z;
    const int bz = z & bMask;
    const int m0 = blockIdx.y * 128;
    const int n0 = blockIdx.x * 128;

    const long Kb   = (long)K * 2;
    const long Aoff = ((long)z  * M + m0) * K;
    const long Boff = ((long)bz * N + n0) * K;

    const char* p0 = (const char*)(A0 + Aoff);
    const char* p1 = (const char*)(SPLIT_B ? (B0 + Boff) : (A1 + Aoff));
    const char* p2 = (const char*)(SPLIT_B ? (B1 + Boff) : (B0 + Boff));

    // cp.async mapping: id in [0,1024) -> row=id>>3, chunk=id&7 (16B chunks)
    uint32_t soffv[4]; long goffv[4];
#pragma unroll
    for (int i = 0; i < 4; i++) {
        int id = t + i * 256;
        int r = id >> 3, c = id & 7;
        soffv[i] = r * 128 + ((uint32_t)(c ^ (r & 7)) << 4);
        goffv[i] = (long)r * Kb + c * 16;
    }

    // ldmatrix invariants
    uint32_t roA[4]; int swA[4];
#pragma unroll
    for (int mi = 0; mi < 4; mi++) {
        int row = wr * 64 + mi * 16 + (lane & 15);
        roA[mi] = row * 128;
        swA[mi] = row & 7;
    }
    const int a_kc = lane >> 4;
    uint32_t roB[2]; int swB[2];
#pragma unroll
    for (int nj = 0; nj < 2; nj++) {
        int row = wc * 32 + nj * 16 + (lane & 7) + ((lane >> 4) << 3);
        roB[nj] = row * 128;
        swB[nj] = row & 7;
    }
    const int b_kc = (lane >> 3) & 1;

    float acc[4][4][4];
#pragma unroll
    for (int mi = 0; mi < 4; mi++)
#pragma unroll
        for (int ni = 0; ni < 4; ni++)
#pragma unroll
            for (int r = 0; r < 4; r++) acc[mi][ni][r] = 0.f;

    const int nch = K >> 6;

    auto load_chunk = [&](int ch, int buf) {
        const uint32_t s = sb + buf * STAGE_SZ;
        const long gk = (long)ch * 128;     // 64 halves = 128 B
#pragma unroll
        for (int i = 0; i < 4; i++) {
            CP16(s + OFF_P0 + soffv[i], p0 + goffv[i] + gk);
            CP16(s + OFF_P1 + soffv[i], p1 + goffv[i] + gk);
            CP16(s + OFF_P2 + soffv[i], p2 + goffv[i] + gk);
        }
        CP_COMMIT();
    };

    load_chunk(0, 0);

    for (int ch = 0; ch < nch; ch++) {
        const int buf = ch & 1;
        if (ch + 1 < nch) { load_chunk(ch + 1, (ch + 1) & 1); CP_WAIT1(); }
        else              { CP_WAIT0(); }
        __syncthreads();

        const uint32_t sP0 = sb + buf * STAGE_SZ + OFF_P0;
        const uint32_t sP1 = sb + buf * STAGE_SZ + OFF_P1;
        const uint32_t sP2 = sb + buf * STAGE_SZ + OFF_P2;

#pragma unroll
        for (int ks = 0; ks < 4; ks++) {
            const int kcA = ks * 2 + a_kc;
            const int kcB = ks * 2 + b_kc;

            uint32_t a0[4][4];
#pragma unroll
            for (int mi = 0; mi < 4; mi++)
                LDSM4(a0[mi][0], a0[mi][1], a0[mi][2], a0[mi][3],
                      sP0 + roA[mi] + ((uint32_t)(kcA ^ swA[mi]) << 4));

            if (!SPLIT_B) {
                uint32_t a1[4][4], b[4][2];
#pragma unroll
                for (int mi = 0; mi < 4; mi++)
                    LDSM4(a1[mi][0], a1[mi][1], a1[mi][2], a1[mi][3],
                          sP1 + roA[mi] + ((uint32_t)(kcA ^ swA[mi]) << 4));
#pragma unroll
                for (int nj = 0; nj < 2; nj++)
                    LDSM4(b[nj*2][0], b[nj*2][1], b[nj*2+1][0], b[nj*2+1][1],
                          sP2 + roB[nj] + ((uint32_t)(kcB ^ swB[nj]) << 4));
#pragma unroll
                for (int mi = 0; mi < 4; mi++)
#pragma unroll
                    for (int ni = 0; ni < 4; ni++)
                        MMAH(acc[mi][ni], a0[mi], b[ni]);
#pragma unroll
                for (int mi = 0; mi < 4; mi++)
#pragma unroll
                    for (int ni = 0; ni < 4; ni++)
                        MMAH(acc[mi][ni], a1[mi], b[ni]);
            } else {
                uint32_t b1[4][2], b2[4][2];
#pragma unroll
                for (int nj = 0; nj < 2; nj++) {
                    uint32_t off = roB[nj] + ((uint32_t)(kcB ^ swB[nj]) << 4);
                    LDSM4(b1[nj*2][0], b1[nj*2][1], b1[nj*2+1][0], b1[nj*2+1][1], sP1 + off);
                    LDSM4(b2[nj*2][0], b2[nj*2][1], b2[nj*2+1][0], b2[nj*2+1][1], sP2 + off);
                }
#pragma unroll
                for (int mi = 0; mi < 4; mi++)
#pragma unroll
                    for (int ni = 0; ni < 4; ni++)
                        MMAH(acc[mi][ni], a0[mi], b1[ni]);
#pragma unroll
                for (int mi = 0; mi < 4; mi++)
#pragma unroll
                    for (int ni = 0; ni < 4; ni++)
                        MMAH(acc[mi][ni], a0[mi], b2[ni]);
            }
        }
        __syncthreads();
    }

    // ---------------- epilogue: acc -> padded smem stage -> coalesced out
    float* stg = reinterpret_cast<float*>(smem);
    {
        const int grp = lane >> 2;
        const int tq  = lane & 3;
#pragma unroll
        for (int mi = 0; mi < 4; mi++) {
            const int m = wr * 64 + mi * 16 + grp;
#pragma unroll
            for (int ni = 0; ni < 4; ni++) {
                const int n = wc * 32 + ni * 8 + 2 * tq;
                stg[m * STG_LD + n]           = acc[mi][ni][0];
                stg[m * STG_LD + n + 1]       = acc[mi][ni][1];
                stg[(m + 8) * STG_LD + n]     = acc[mi][ni][2];
                stg[(m + 8) * STG_LD + n + 1] = acc[mi][ni][3];
            }
        }
    }
    __syncthreads();

    const float* brow = HAS_BIAS ? (bias + (long)bz * N + n0) : nullptr;

    if (OUT_MODE == 0) {
#pragma unroll
        for (int r = 0; r < 64; r++) {
            int idx = r * 256 + t;
            int m = idx >> 7, n = idx & 127;
            float v = stg[m * STG_LD + n];
            if (HAS_BIAS) v = fmaxf(v + brow[n], 0.f) * scale;
            OutF[((long)z * M + m0 + m) * N + n0 + n] = v;
        }
    } else if (OUT_MODE == 1 || OUT_MODE == 3) {
#pragma unroll
        for (int r = 0; r < 32; r++) {
            int idx = r * 256 + t;
            int m = idx >> 6, j = idx & 63;
            int n = 2 * j;
            float v0 = stg[m * STG_LD + n];
            float v1 = stg[m * STG_LD + n + 1];
            if (HAS_BIAS) {
                v0 = fmaxf(v0 + brow[n], 0.f) * scale;
                v1 = fmaxf(v1 + brow[n + 1], 0.f) * scale;
            }
            long base = ((long)z * M + m0 + m) * N + n0 + n;
            if (OUT_MODE == 3) {
                __half2 H; H.x = __float2half(v0); H.y = __float2half(v1);
                *reinterpret_cast<__half2*>(&OutH[base]) = H;
            } else {
                half h0, l0, h1, l1;
                split2h(v0, h0, l0); split2h(v1, h1, l1);
                __half2 H; H.x = h0; H.y = h1;
                __half2 L; L.x = l0; L.y = l1;
                *reinterpret_cast<__half2*>(&OutH[base]) = H;
                *reinterpret_cast<__half2*>(&OutL[base]) = L;
            }
        }
    } else {   // OUT_MODE == 2: split fp16, transposed Out[z][N][M]
#pragma unroll
        for (int r = 0; r < 32; r++) {
            int idx = r * 256 + t;
            int e = idx >> 6, j = idx & 63;
            int q = 2 * j;
            float v0 = stg[q * STG_LD + e];
            float v1 = stg[(q + 1) * STG_LD + e];
            if (HAS_BIAS) {
                float bv = brow[e];
                v0 = fmaxf(v0 + bv, 0.f) * scale;
                v1 = fmaxf(v1 + bv, 0.f) * scale;
            }
            half h0, l0, h1, l1;
            split2h(v0, h0, l0); split2h(v1, h1, l1);
            long base = ((long)z * N + n0 + e) * M + m0 + q;
            __half2 H; H.x = h0; H.y = h1;
            __half2 L; L.x = l0; L.y = l1;
            *reinterpret_cast<__half2*>(&OutH[base]) = H;
            *reinterpret_cast<__half2*>(&OutL[base]) = L;
        }
    }
}

// ---------------------------------------------------------------- elementwise
// Fused: context computation + split of BOTH ctx and query into fp16 hi/lo.
// One thread per (b,p,d-pair).
__global__ __launch_bounds__(256) void ctx_qry_split_kernel(
        const float* __restrict__ q, const float* __restrict__ aw,
        half* __restrict__ qryH, half* __restrict__ qryL,
        half* __restrict__ ctxH, half* __restrict__ ctxL)
{
    int idx = blockIdx.x * 256 + threadIdx.x;      // over BPD/2
    if (idx >= BPD / 2) return;
    int dp = idx & 127;            // d pair index
    int p  = (idx >> 7) & 511;
    int b  = idx >> 16;

    float2 qv[C_], pr[C_];
    float2 accv = make_float2(0.f, 0.f);
#pragma unroll
    for (int c = 0; c < C_; c++) {
        long qo = ((long)((b * C_ + c) * P_ + p)) * D_ + 2 * dp;
        long ao = ((long)(c * P_ + p)) * D_ + 2 * dp;
        float2 qq = *reinterpret_cast<const float2*>(&q[qo]);
        float2 w  = *reinterpret_cast<const float2*>(&aw[ao]);
        qv[c] = qq;
        pr[c].x = w.x * qq.x; pr[c].y = w.y * qq.y;
        accv.x += pr[c].x;    accv.y += pr[c].y;
    }
#pragma unroll
    for (int c = 0; c < C_; c++) {
        long o = ((long)((b * C_ + c) * P_ + p)) * D_ + 2 * dp;
        float c0 = accv.x - pr[c].x, c1 = accv.y - pr[c].y;
        half h0, l0, h1, l1;
        split2h(c0, h0, l0); split2h(c1, h1, l1);
        __half2 H; H.x = h0; H.y = h1;
        __half2 L; L.x = l0; L.y = l1;
        *reinterpret_cast<__half2*>(&ctxH[o]) = H;
        *reinterpret_cast<__half2*>(&ctxL[o]) = L;
        split2h(qv[c].x, h0, l0); split2h(qv[c].y, h1, l1);
        __half2 QH; QH.x = h0; QH.y = h1;
        __half2 QL; QL.x = l0; QL.y = l1;
        *reinterpret_cast<__half2*>(&qryH[o]) = QH;
        *reinterpret_cast<__half2*>(&qryL[o]) = QL;
    }
}

// W[c][d][e] -> WT[c][e][d] fp16 single, tiled smem transpose.
__global__ __launch_bounds__(256) void split_wT_kernel(const float* __restrict__ w,
                                                       half* __restrict__ wT)
{
    __shared__ float s[32][33];
    int bc = blockIdx.x >> 6;
    int t6 = blockIdx.x & 63;
    int e0 = (t6 >> 3) * 32, d0 = (t6 & 7) * 32;
    int tx = threadIdx.x & 31, ty = threadIdx.x >> 5;
#pragma unroll
    for (int r = 0; r < 4; r++) {
        int row = ty + r * 8;                       // d index
        s[row][tx] = w[((long)bc * 256 + d0 + row) * 256 + e0 + tx];
    }
    __syncthreads();
#pragma unroll
    for (int r = 0; r < 4; r++) {
        int row = ty + r * 8;                       // e index
        wT[((long)bc * 256 + e0 + row) * 256 + d0 + tx] = __float2half(s[tx][row]);
    }
}

// softmax over rows of 512 fp32 -> single fp16 attn
__global__ __launch_bounds__(256) void softmax_half_kernel(const float* __restrict__ s,
        half* __restrict__ attn, long nrows)
{
    long row = (long)blockIdx.x * 8 + (threadIdx.x >> 5);
    if (row >= nrows) return;
    int lane = threadIdx.x & 31;
    const float2* r = reinterpret_cast<const float2*>(s + row * (long)P_);

    float2 v[8];
    float mx = -INFINITY;
#pragma unroll
    for (int i = 0; i < 8; i++) {
        v[i] = r[lane + i * 32];
        mx = fmaxf(mx, fmaxf(v[i].x, v[i].y));
    }
#pragma unroll
    for (int o = 16; o > 0; o >>= 1)
        mx = fmaxf(mx, __shfl_xor_sync(0xffffffffu, mx, o));
    float sum = 0.f;
#pragma unroll
    for (int i = 0; i < 8; i++) {
        v[i].x = __expf(v[i].x - mx);
        v[i].y = __expf(v[i].y - mx);
        sum += v[i].x + v[i].y;
    }
#pragma unroll
    for (int o = 16; o > 0; o >>= 1)
        sum += __shfl_xor_sync(0xffffffffu, sum, o);
    float inv = 1.f / sum;
    __half2* ob = reinterpret_cast<__half2*>(attn + row * (long)P_);
#pragma unroll
    for (int i = 0; i < 8; i++) {
        __half2 h; h.x = __float2half(v[i].x * inv); h.y = __float2half(v[i].y * inv);
        ob[lane + i * 32] = h;
    }
}

// ---------------------------------------------------------------- launcher
extern "C" void kernel_launch(void* const* d_in, const int* in_sizes, int n_in,
                              void* d_out, int out_size)
{
    const float* query = (const float*)d_in[0];
    const float* aw    = (const float*)d_in[1];
    const float* qw    = (const float*)d_in[2];
    const float* kw    = (const float*)d_in[3];
    const float* vw    = (const float*)d_in[4];
    const float* qb    = (const float*)d_in[5];
    const float* kb    = (const float*)d_in[6];
    const float* vb    = (const float*)d_in[7];
    float* out = (float*)d_out;

    half *qryH, *qryL, *ctxH, *ctxL, *qH, *qL, *kS, *vTH, *vTL, *attn;
    half *wqT, *wkT, *wvT;
    float* scores;
    cudaGetSymbolAddress((void**)&qryH, g_qry_hi); cudaGetSymbolAddress((void**)&qryL, g_qry_lo);
    cudaGetSymbolAddress((void**)&ctxH, g_ctx_hi); cudaGetSymbolAddress((void**)&ctxL, g_ctx_lo);
    cudaGetSymbolAddress((void**)&qH, g_q_hi);     cudaGetSymbolAddress((void**)&qL, g_q_lo);
    cudaGetSymbolAddress((void**)&kS, g_k);
    cudaGetSymbolAddress((void**)&vTH, g_vT_hi);   cudaGetSymbolAddress((void**)&vTL, g_vT_lo);
    cudaGetSymbolAddress((void**)&attn, g_attn);
    cudaGetSymbolAddress((void**)&wqT, g_wqT);
    cudaGetSymbolAddress((void**)&wkT, g_wkT);
    cudaGetSymbolAddress((void**)&wvT, g_wvT);
    cudaGetSymbolAddress((void**)&scores, g_scores);

    cudaFuncSetAttribute(mma_gemm<0,1,1>, cudaFuncAttributeMaxDynamicSharedMemorySize, SMEM_SZ);
    cudaFuncSetAttribute(mma_gemm<0,1,3>, cudaFuncAttributeMaxDynamicSharedMemorySize, SMEM_SZ);
    cudaFuncSetAttribute(mma_gemm<0,1,2>, cudaFuncAttributeMaxDynamicSharedMemorySize, SMEM_SZ);
    cudaFuncSetAttribute(mma_gemm<0,0,0>, cudaFuncAttributeMaxDynamicSharedMemorySize, SMEM_SZ);
    cudaFuncSetAttribute(mma_gemm<1,0,0>, cudaFuncAttributeMaxDynamicSharedMemorySize, SMEM_SZ);

    // 1) fused context + query split; weight transposes
    ctx_qry_split_kernel<<<BPD / 2 / 256, 256>>>(query, aw, qryH, qryL, ctxH, ctxL);
    split_wT_kernel<<<1024, 256>>>(qw, wqT);
    split_wT_kernel<<<1024, 256>>>(kw, wkT);
    split_wT_kernel<<<1024, 256>>>(vw, wvT);

    const float qscale = 0.0625f;  // D^-1/2

    // 2) q = relu(query@Wq + bq) * qscale -> fp16 hi/lo   M=512 N=256 K=256
    {
        dim3 g(D_ / 128, P_ / 128, Z_);
        mma_gemm<0,1,1><<<g, 256, SMEM_SZ>>>(
            qryH, qryL, wqT, nullptr, qb, qH, qL, nullptr, P_, D_, D_, 15, qscale);
    }
    // 3) k = relu(ctx@Wk + bk) -> single fp16
    {
        dim3 g(D_ / 128, P_ / 128, Z_);
        mma_gemm<0,1,3><<<g, 256, SMEM_SZ>>>(
            ctxH, ctxL, wkT, nullptr, kb, kS, nullptr, nullptr, P_, D_, D_, 15, 1.0f);
    }
    // 4) v = relu(ctx@Wv + bv) -> fp16 hi/lo transposed [z][e][q]
    {
        dim3 g(D_ / 128, P_ / 128, Z_);
        mma_gemm<0,1,2><<<g, 256, SMEM_SZ>>>(
            ctxH, ctxL, wvT, nullptr, vb, vTH, vTL, nullptr, P_, D_, D_, 15, 1.0f);
    }
    // 5) scores = q @ k^T -> fp32   M=512 N=512 K=256
    {
        dim3 g(P_ / 128, P_ / 128, Z_);
        mma_gemm<0,0,0><<<g, 256, SMEM_SZ>>>(
            qH, qL, kS, nullptr, nullptr, nullptr, nullptr, scores, P_, P_, D_, 255, 1.0f);
    }
    // 6) softmax -> single fp16 attn
    {
        long nrows = (long)B_ * C_ * P_;
        softmax_half_kernel<<<(int)((nrows + 7) / 8), 256>>>(scores, attn, nrows);
    }
    // 7) out = attn @ (vThi+vTlo)^T -> fp32   M=512 N=256 K=512
    {
        dim3 g(D_ / 128, P_ / 128, Z_);
        mma_gemm<1,0,0><<<g, 256, SMEM_SZ>>>(
            attn, nullptr, vTH, vTL, nullptr, nullptr, nullptr, out, P_, D_, P_, 255, 1.0f);
    }
}

// round 6
// speedup vs baseline: 4.6937x; 1.3971x over previous
#include <cuda_runtime.h>
#include <cuda_fp16.h>
#include <cstdint>
#include <math.h>

// ---------------------------------------------------------------- dims
#define B_  16
#define C_  16
#define P_  512
#define D_  256
#define Z_  (B_*C_)            // 256 batches
#define BCPD (B_*C_*P_*D_)     // 33,554,432
#define BPD  (B_*P_*D_)        // 2,097,152
#define BCPP (B_*C_*P_*P_)     // 67,108,864
#define WELEM (C_*D_*D_)       // 1,048,576

// ---------------------------------------------------------------- scratch
__device__ half g_qry[BCPD];
__device__ half g_ctx[BCPD];
__device__ half g_q[BCPD];
__device__ half g_k[BCPD];
__device__ half g_vT[BCPD];
__device__ half g_attn[BCPP];
__device__ float g_scores[BCPP];
__device__ half g_wqT[WELEM], g_wkT[WELEM], g_wvT[WELEM];

// ---------------------------------------------------------------- helpers
__device__ __forceinline__ uint32_t smem_u32(const void* p) {
    uint32_t a;
    asm("{ .reg .u64 t; cvta.to.shared.u64 t, %1; cvt.u32.u64 %0, t; }" : "=r"(a) : "l"(p));
    return a;
}

#define CP16(saddr, gaddr) \
    asm volatile("cp.async.cg.shared.global [%0], [%1], 16;" :: "r"(saddr), "l"(gaddr) : "memory")
#define CP_COMMIT() asm volatile("cp.async.commit_group;" ::: "memory")
#define CP_WAIT1()  asm volatile("cp.async.wait_group 1;" ::: "memory")
#define CP_WAIT0()  asm volatile("cp.async.wait_group 0;" ::: "memory")

#define LDSM4(r0, r1, r2, r3, addr) \
    asm volatile("ldmatrix.sync.aligned.m8n8.x4.shared.b16 {%0,%1,%2,%3}, [%4];" \
        : "=r"(r0), "=r"(r1), "=r"(r2), "=r"(r3) : "r"(addr))

#define MMAH(c, a, b) \
    asm volatile("mma.sync.aligned.m16n8k16.row.col.f32.f16.f16.f32 " \
        "{%0,%1,%2,%3}, {%4,%5,%6,%7}, {%8,%9}, {%0,%1,%2,%3};" \
        : "+f"((c)[0]), "+f"((c)[1]), "+f"((c)[2]), "+f"((c)[3]) \
        : "r"((a)[0]), "r"((a)[1]), "r"((a)[2]), "r"((a)[3]), "r"((b)[0]), "r"((b)[1]))

// ---------------------------------------------------------------- smem layout
// K-chunk = 64: each piece = 128 rows x 128B (swizzled). 2 pieces/stage.
#define OFF_A    0
#define OFF_B    16384
#define STAGE_SZ 32768
#define SMEM_SZ  66560      // 2 stages (64KB); epilogue stage 128x130 fp32
#define STG_LD   130

// ---------------------------------------------------------------- GEMM
// D = A @ B^T, fp16 inputs, fp32 accumulate. CTA tile 128x128, K-chunk 64.
// A: [z][M][K] fp16 K-major; B: [bz][N][K] fp16 K-major.
// OUT_MODE: 0 = fp32, 1 = fp16, 2 = fp16 transposed (Out[z][N][M]).
template<int HAS_BIAS, int OUT_MODE>
__global__ __launch_bounds__(256, 2)
void mma_gemm(const half* __restrict__ A, const half* __restrict__ B,
              const float* __restrict__ bias,
              half* __restrict__ OutH, float* __restrict__ OutF,
              int M, int N, int K, int bMask, float scale)
{
    extern __shared__ char smem[];
    const uint32_t sb = smem_u32(smem);

    const int t    = threadIdx.x;
    const int wid  = t >> 5;
    const int lane = t & 31;
    const int wr   = wid >> 2;      // 0..1
    const int wc   = wid & 3;       // 0..3

    const int z  = blockIdx.z;
    const int bz = z & bMask;
    const int m0 = blockIdx.y * 128;
    const int n0 = blockIdx.x * 128;

    const long Kb = (long)K * 2;
    const char* gA = (const char*)(A + ((long)z  * M + m0) * K);
    const char* gB = (const char*)(B + ((long)bz * N + n0) * K);

    // cp.async mapping: id in [0,1024) -> row=id>>3, chunk=id&7 (16B chunks)
    uint32_t soffv[4]; long goffv[4];
#pragma unroll
    for (int i = 0; i < 4; i++) {
        int id = t + i * 256;
        int r = id >> 3, c = id & 7;
        soffv[i] = r * 128 + ((uint32_t)(c ^ (r & 7)) << 4);
        goffv[i] = (long)r * Kb + c * 16;
    }

    // ldmatrix invariants
    uint32_t roA[4]; int swA[4];
#pragma unroll
    for (int mi = 0; mi < 4; mi++) {
        int row = wr * 64 + mi * 16 + (lane & 15);
        roA[mi] = row * 128;
        swA[mi] = row & 7;
    }
    const int a_kc = lane >> 4;
    uint32_t roB[2]; int swB[2];
#pragma unroll
    for (int nj = 0; nj < 2; nj++) {
        int row = wc * 32 + nj * 16 + (lane & 7) + ((lane >> 4) << 3);
        roB[nj] = row * 128;
        swB[nj] = row & 7;
    }
    const int b_kc = (lane >> 3) & 1;

    float acc[4][4][4];
#pragma unroll
    for (int mi = 0; mi < 4; mi++)
#pragma unroll
        for (int ni = 0; ni < 4; ni++)
#pragma unroll
            for (int r = 0; r < 4; r++) acc[mi][ni][r] = 0.f;

    const int nch = K >> 6;

    auto load_chunk = [&](int ch, int buf) {
        const uint32_t s = sb + buf * STAGE_SZ;
        const long gk = (long)ch * 128;     // 64 halves = 128 B
#pragma unroll
        for (int i = 0; i < 4; i++) {
            CP16(s + OFF_A + soffv[i], gA + goffv[i] + gk);
            CP16(s + OFF_B + soffv[i], gB + goffv[i] + gk);
        }
        CP_COMMIT();
    };

    load_chunk(0, 0);

    for (int ch = 0; ch < nch; ch++) {
        const int buf = ch & 1;
        if (ch + 1 < nch) { load_chunk(ch + 1, (ch + 1) & 1); CP_WAIT1(); }
        else              { CP_WAIT0(); }
        __syncthreads();

        const uint32_t sA = sb + buf * STAGE_SZ + OFF_A;
        const uint32_t sB = sb + buf * STAGE_SZ + OFF_B;

#pragma unroll
        for (int ks = 0; ks < 4; ks++) {
            const int kcA = ks * 2 + a_kc;
            const int kcB = ks * 2 + b_kc;

            uint32_t a[4][4], b[4][2];
#pragma unroll
            for (int mi = 0; mi < 4; mi++)
                LDSM4(a[mi][0], a[mi][1], a[mi][2], a[mi][3],
                      sA + roA[mi] + ((uint32_t)(kcA ^ swA[mi]) << 4));
#pragma unroll
            for (int nj = 0; nj < 2; nj++)
                LDSM4(b[nj*2][0], b[nj*2][1], b[nj*2+1][0], b[nj*2+1][1],
                      sB + roB[nj] + ((uint32_t)(kcB ^ swB[nj]) << 4));
#pragma unroll
            for (int mi = 0; mi < 4; mi++)
#pragma unroll
                for (int ni = 0; ni < 4; ni++)
                    MMAH(acc[mi][ni], a[mi], b[ni]);
        }
        __syncthreads();
    }

    // ---------------- epilogue: acc -> padded smem stage -> coalesced out
    float* stg = reinterpret_cast<float*>(smem);
    {
        const int grp = lane >> 2;
        const int tq  = lane & 3;
#pragma unroll
        for (int mi = 0; mi < 4; mi++) {
            const int m = wr * 64 + mi * 16 + grp;
#pragma unroll
            for (int ni = 0; ni < 4; ni++) {
                const int n = wc * 32 + ni * 8 + 2 * tq;
                stg[m * STG_LD + n]           = acc[mi][ni][0];
                stg[m * STG_LD + n + 1]       = acc[mi][ni][1];
                stg[(m + 8) * STG_LD + n]     = acc[mi][ni][2];
                stg[(m + 8) * STG_LD + n + 1] = acc[mi][ni][3];
            }
        }
    }
    __syncthreads();

    const float* brow = HAS_BIAS ? (bias + (long)bz * N + n0) : nullptr;

    if (OUT_MODE == 0) {
#pragma unroll
        for (int r = 0; r < 64; r++) {
            int idx = r * 256 + t;
            int m = idx >> 7, n = idx & 127;
            float v = stg[m * STG_LD + n];
            if (HAS_BIAS) v = fmaxf(v + brow[n], 0.f) * scale;
            OutF[((long)z * M + m0 + m) * N + n0 + n] = v;
        }
    } else if (OUT_MODE == 1) {
#pragma unroll
        for (int r = 0; r < 32; r++) {
            int idx = r * 256 + t;
            int m = idx >> 6, j = idx & 63;
            int n = 2 * j;
            float v0 = stg[m * STG_LD + n];
            float v1 = stg[m * STG_LD + n + 1];
            if (HAS_BIAS) {
                v0 = fmaxf(v0 + brow[n], 0.f) * scale;
                v1 = fmaxf(v1 + brow[n + 1], 0.f) * scale;
            }
            long base = ((long)z * M + m0 + m) * N + n0 + n;
            __half2 H; H.x = __float2half(v0); H.y = __float2half(v1);
            *reinterpret_cast<__half2*>(&OutH[base]) = H;
        }
    } else {   // OUT_MODE == 2: fp16 transposed Out[z][N][M]
#pragma unroll
        for (int r = 0; r < 32; r++) {
            int idx = r * 256 + t;
            int e = idx >> 6, j = idx & 63;
            int q = 2 * j;
            float v0 = stg[q * STG_LD + e];
            float v1 = stg[(q + 1) * STG_LD + e];
            if (HAS_BIAS) {
                float bv = brow[e];
                v0 = fmaxf(v0 + bv, 0.f) * scale;
                v1 = fmaxf(v1 + bv, 0.f) * scale;
            }
            long base = ((long)z * N + n0 + e) * M + m0 + q;
            __half2 H; H.x = __float2half(v0); H.y = __float2half(v1);
            *reinterpret_cast<__half2*>(&OutH[base]) = H;
        }
    }
}

// ---------------------------------------------------------------- elementwise
// Fused: context computation + fp16 conversion of BOTH ctx and query.
__global__ __launch_bounds__(256) void ctx_qry_kernel(
        const float* __restrict__ q, const float* __restrict__ aw,
        half* __restrict__ qry16, half* __restrict__ ctx16)
{
    int idx = blockIdx.x * 256 + threadIdx.x;      // over BPD/2
    if (idx >= BPD / 2) return;
    int dp = idx & 127;            // d pair index
    int p  = (idx >> 7) & 511;
    int b  = idx >> 16;

    float2 qv[C_], pr[C_];
    float2 accv = make_float2(0.f, 0.f);
#pragma unroll
    for (int c = 0; c < C_; c++) {
        long qo = ((long)((b * C_ + c) * P_ + p)) * D_ + 2 * dp;
        long ao = ((long)(c * P_ + p)) * D_ + 2 * dp;
        float2 qq = *reinterpret_cast<const float2*>(&q[qo]);
        float2 w  = *reinterpret_cast<const float2*>(&aw[ao]);
        qv[c] = qq;
        pr[c].x = w.x * qq.x; pr[c].y = w.y * qq.y;
        accv.x += pr[c].x;    accv.y += pr[c].y;
    }
#pragma unroll
    for (int c = 0; c < C_; c++) {
        long o = ((long)((b * C_ + c) * P_ + p)) * D_ + 2 * dp;
        __half2 Cv; Cv.x = __float2half(accv.x - pr[c].x);
        Cv.y = __float2half(accv.y - pr[c].y);
        *reinterpret_cast<__half2*>(&ctx16[o]) = Cv;
        __half2 Qv; Qv.x = __float2half(qv[c].x);
        Qv.y = __float2half(qv[c].y);
        *reinterpret_cast<__half2*>(&qry16[o]) = Qv;
    }
}

// W[c][d][e] -> WT[c][e][d] fp16, tiled smem transpose.
__global__ __launch_bounds__(256) void split_wT_kernel(const float* __restrict__ w,
                                                       half* __restrict__ wT)
{
    __shared__ float s[32][33];
    int bc = blockIdx.x >> 6;
    int t6 = blockIdx.x & 63;
    int e0 = (t6 >> 3) * 32, d0 = (t6 & 7) * 32;
    int tx = threadIdx.x & 31, ty = threadIdx.x >> 5;
#pragma unroll
    for (int r = 0; r < 4; r++) {
        int row = ty + r * 8;                       // d index
        s[row][tx] = w[((long)bc * 256 + d0 + row) * 256 + e0 + tx];
    }
    __syncthreads();
#pragma unroll
    for (int r = 0; r < 4; r++) {
        int row = ty + r * 8;                       // e index
        wT[((long)bc * 256 + e0 + row) * 256 + d0 + tx] = __float2half(s[tx][row]);
    }
}

// softmax over rows of 512 fp32 -> single fp16 attn
__global__ __launch_bounds__(256) void softmax_half_kernel(const float* __restrict__ s,
        half* __restrict__ attn, long nrows)
{
    long row = (long)blockIdx.x * 8 + (threadIdx.x >> 5);
    if (row >= nrows) return;
    int lane = threadIdx.x & 31;
    const float2* r = reinterpret_cast<const float2*>(s + row * (long)P_);

    float2 v[8];
    float mx = -INFINITY;
#pragma unroll
    for (int i = 0; i < 8; i++) {
        v[i] = r[lane + i * 32];
        mx = fmaxf(mx, fmaxf(v[i].x, v[i].y));
    }
#pragma unroll
    for (int o = 16; o > 0; o >>= 1)
        mx = fmaxf(mx, __shfl_xor_sync(0xffffffffu, mx, o));
    float sum = 0.f;
#pragma unroll
    for (int i = 0; i < 8; i++) {
        v[i].x = __expf(v[i].x - mx);
        v[i].y = __expf(v[i].y - mx);
        sum += v[i].x + v[i].y;
    }
#pragma unroll
    for (int o = 16; o > 0; o >>= 1)
        sum += __shfl_xor_sync(0xffffffffu, sum, o);
    float inv = 1.f / sum;
    __half2* ob = reinterpret_cast<__half2*>(attn + row * (long)P_);
#pragma unroll
    for (int i = 0; i < 8; i++) {
        __half2 h; h.x = __float2half(v[i].x * inv); h.y = __float2half(v[i].y * inv);
        ob[lane + i * 32] = h;
    }
}

// ---------------------------------------------------------------- launcher
extern "C" void kernel_launch(void* const* d_in, const int* in_sizes, int n_in,
                              void* d_out, int out_size)
{
    const float* query = (const float*)d_in[0];
    const float* aw    = (const float*)d_in[1];
    const float* qw    = (const float*)d_in[2];
    const float* kw    = (const float*)d_in[3];
    const float* vw    = (const float*)d_in[4];
    const float* qb    = (const float*)d_in[5];
    const float* kb    = (const float*)d_in[6];
    const float* vb    = (const float*)d_in[7];
    float* out = (float*)d_out;

    half *qry16, *ctx16, *qB, *kB, *vT, *attn;
    half *wqT, *wkT, *wvT;
    float* scores;
    cudaGetSymbolAddress((void**)&qry16, g_qry);
    cudaGetSymbolAddress((void**)&ctx16, g_ctx);
    cudaGetSymbolAddress((void**)&qB, g_q);
    cudaGetSymbolAddress((void**)&kB, g_k);
    cudaGetSymbolAddress((void**)&vT, g_vT);
    cudaGetSymbolAddress((void**)&attn, g_attn);
    cudaGetSymbolAddress((void**)&wqT, g_wqT);
    cudaGetSymbolAddress((void**)&wkT, g_wkT);
    cudaGetSymbolAddress((void**)&wvT, g_wvT);
    cudaGetSymbolAddress((void**)&scores, g_scores);

    cudaFuncSetAttribute(mma_gemm<1,1>, cudaFuncAttributeMaxDynamicSharedMemorySize, SMEM_SZ);
    cudaFuncSetAttribute(mma_gemm<1,2>, cudaFuncAttributeMaxDynamicSharedMemorySize, SMEM_SZ);
    cudaFuncSetAttribute(mma_gemm<0,0>, cudaFuncAttributeMaxDynamicSharedMemorySize, SMEM_SZ);

    // 1) fused context + query fp16 conversion; weight transposes
    ctx_qry_kernel<<<BPD / 2 / 256, 256>>>(query, aw, qry16, ctx16);
    split_wT_kernel<<<1024, 256>>>(qw, wqT);
    split_wT_kernel<<<1024, 256>>>(kw, wkT);
    split_wT_kernel<<<1024, 256>>>(vw, wvT);

    const float qscale = 0.0625f;  // D^-1/2

    // 2) q = relu(query@Wq + bq) * qscale -> fp16   M=512 N=256 K=256
    {
        dim3 g(D_ / 128, P_ / 128, Z_);
        mma_gemm<1,1><<<g, 256, SMEM_SZ>>>(
            qry16, wqT, qb, qB, nullptr, P_, D_, D_, 15, qscale);
    }
    // 3) k = relu(ctx@Wk + bk) -> fp16
    {
        dim3 g(D_ / 128, P_ / 128, Z_);
        mma_gemm<1,1><<<g, 256, SMEM_SZ>>>(
            ctx16, wkT, kb, kB, nullptr, P_, D_, D_, 15, 1.0f);
    }
    // 4) v = relu(ctx@Wv + bv) -> fp16 transposed [z][e][q]
    {
        dim3 g(D_ / 128, P_ / 128, Z_);
        mma_gemm<1,2><<<g, 256, SMEM_SZ>>>(
            ctx16, wvT, vb, vT, nullptr, P_, D_, D_, 15, 1.0f);
    }
    // 5) scores = q @ k^T -> fp32   M=512 N=512 K=256
    {
        dim3 g(P_ / 128, P_ / 128, Z_);
        mma_gemm<0,0><<<g, 256, SMEM_SZ>>>(
            qB, kB, nullptr, nullptr, scores, P_, P_, D_, 255, 1.0f);
    }
    // 6) softmax -> fp16 attn
    {
        long nrows = (long)B_ * C_ * P_;
        softmax_half_kernel<<<(int)((nrows + 7) / 8), 256>>>(scores, attn, nrows);
    }
    // 7) out = attn @ vT^T -> fp32   M=512 N=256 K=512
    {
        dim3 g(D_ / 128, P_ / 128, Z_);
        mma_gemm<0,0><<<g, 256, SMEM_SZ>>>(
            attn, vT, nullptr, nullptr, out, P_, D_, P_, 255, 1.0f);
    }
}